// round 15
// baseline (speedup 1.0000x reference)
#include <cuda_runtime.h>
#include <cuda_fp16.h>
#include <cstdint>
#include <math.h>

#define EMBED 256
#define PAIRS 15
#define MROWS 16384
#define KPAIR 512
#define KFIN  3840

#define BM 32
#define KC 32
#define NTHREADS 256
#define PITCH 80                          // A smem row: 32 fp16 = 64B + 16B pad
#define ATILE (BM * PITCH)                // 2560 B
#define PITCHB 528                        // B smem row: 256 fp16 = 512B + 16B pad
#define BTILE (KC * PITCHB)               // 16896 B   [k][n] natural layout
#define BUFB  (ATILE + BTILE)             // 19456 B
#define HPITCH 528
#define HOFF  (3 * BUFB)                  // 58368
#define SMEM_BYTES (HOFF + BM * HPITCH)   // 75264  (x2 CTAs = 150528 < 228KB)

#define NCH1 (KPAIR / KC)                 // 16
#define NCH2 (EMBED / KC)                 // 8

// ---- fp16 weights, original [k][n] layouts (allocation-guard-safe) ----
static __device__ __half g_Wp16[(size_t)PAIRS * KPAIR * EMBED];  // [p][k][n]
static __device__ __half g_Wf16[(size_t)KFIN * EMBED];           // [k][n]

__constant__ int c_pi[PAIRS] = {0,0,0,0,0,1,1,1,1,2,2,2,3,3,4};
__constant__ int c_pj[PAIRS] = {1,2,3,4,5,2,3,4,5,3,4,5,4,5,5};

__device__ __forceinline__ bool pair_on(const int* __restrict__ NAS, int p) {
    int i = c_pi[p], j = c_pj[p];
    int ni = (i < 2) ? 1 : __ldg(&NAS[i]);
    int nj = (j < 2) ? 1 : __ldg(&NAS[j]);
    return (ni != 0) && (nj != 0);
}
__device__ __forceinline__ uint32_t smem_u32(const void* p) {
    uint32_t a;
    asm("{ .reg .u64 t; cvta.to.shared.u64 t, %1; cvt.u32.u64 %0, t; }" : "=r"(a) : "l"(p));
    return a;
}

// ---- base-target PTX primitives (sm_80 baseline; valid on plain sm_103) ----
__device__ __forceinline__ void cp16(uint32_t dst, const void* src) {
    asm volatile("cp.async.cg.shared.global [%0], [%1], 16;" :: "r"(dst), "l"(src));
}
#define CP_COMMIT()      asm volatile("cp.async.commit_group;" ::: "memory")
#define CP_WAIT(n)       asm volatile("cp.async.wait_group %0;" :: "n"(n) : "memory")
#define LDM_X4(r, addr) \
    asm volatile("ldmatrix.sync.aligned.m8n8.x4.shared.b16 {%0,%1,%2,%3}, [%4];" \
        : "=r"((r)[0]), "=r"((r)[1]), "=r"((r)[2]), "=r"((r)[3]) : "r"(addr))
#define LDM_X4T(r, addr) \
    asm volatile("ldmatrix.sync.aligned.m8n8.x4.trans.shared.b16 {%0,%1,%2,%3}, [%4];" \
        : "=r"((r)[0]), "=r"((r)[1]), "=r"((r)[2]), "=r"((r)[3]) : "r"(addr))
#define MMA(d, a, b0, b1) \
    asm volatile("mma.sync.aligned.m16n8k16.row.col.f32.f16.f16.f32 " \
        "{%0,%1,%2,%3}, {%4,%5,%6,%7}, {%8,%9}, {%0,%1,%2,%3};" \
        : "+f"((d)[0]), "+f"((d)[1]), "+f"((d)[2]), "+f"((d)[3]) \
        : "r"((a)[0]), "r"((a)[1]), "r"((a)[2]), "r"((a)[3]), "r"(b0), "r"(b1))

// ---------------------------------------------------------------------------
// Prep: elementwise fp32 -> fp16 convert, gated on active pairs/segments.
// ---------------------------------------------------------------------------
#define NP1 ((size_t)PAIRS * KPAIR * EMBED)   // 1966080
#define NP2 ((size_t)KFIN * EMBED)            //  983040
__global__ void prep_convert(const float* __restrict__ W_pair,
                             const float* __restrict__ W_final,
                             const int*   __restrict__ NAS) {
    size_t i = ((size_t)blockIdx.x * blockDim.x + threadIdx.x) * 4;
    const float* src; __half* dst; size_t o;
    if (i < NP1) {
        o = i;
        int p = (int)(o / ((size_t)KPAIR * EMBED));
        if (!pair_on(NAS, p)) return;
        src = W_pair; dst = g_Wp16;
    } else {
        o = i - NP1;
        int p = (int)(o >> 8) >> 8;   // k = o/256 ; segment = k/256
        if (!pair_on(NAS, p)) return;
        src = W_final; dst = g_Wf16;
    }
    float4 v = *reinterpret_cast<const float4*>(src + o);
    __half2 h0 = __floats2half2_rn(v.x, v.y);
    __half2 h1 = __floats2half2_rn(v.z, v.w);
    *reinterpret_cast<__half2*>(dst + o)     = h0;
    *reinterpret_cast<__half2*>(dst + o + 2) = h1;
}

// ---------------------------------------------------------------------------
// Loaders
// ---------------------------------------------------------------------------
// A: 32 rows x 32 k fp32 -> fp16; 256 threads (8/row x 4 fp32 each).
__device__ __forceinline__ void sts_cvt(char* smem, int bufofs, uint32_t dofs,
                                        const float4 v) {
    unsigned short h[4];
    h[0] = __half_as_ushort(__float2half_rn(v.x));
    h[1] = __half_as_ushort(__float2half_rn(v.y));
    h[2] = __half_as_ushort(__float2half_rn(v.z));
    h[3] = __half_as_ushort(__float2half_rn(v.w));
    *reinterpret_cast<uint2*>(smem + bufofs + dofs) =
        make_uint2((uint32_t)h[0] | ((uint32_t)h[1] << 16),
                   (uint32_t)h[2] | ((uint32_t)h[3] << 16));
}
// B tile: [32 k][256 n] fp16, contiguous 512B rows; 8 threads/row x 64B.
__device__ __forceinline__ void cp_bk(uint32_t buf, int tid, const __half* bsrc) {
    const int row = tid >> 3, c = tid & 7;
    const uint32_t d = buf + ATILE + row * PITCHB + c * 64;
    const __half* s = bsrc + (size_t)row * EMBED + c * 32;
    cp16(d, s); cp16(d + 16, s + 8); cp16(d + 32, s + 16); cp16(d + 48, s + 24);
}

// ---------------------------------------------------------------------------
// Compute. 8 warps: warpN = wid (32 of 256 cols), all warps cover rows 0..31.
// ---------------------------------------------------------------------------
__device__ __forceinline__ void mma_burst(const uint32_t a[2][2][4],
                                          const uint32_t b[2][2][4],
                                          float acc[2][4][4]) {
    #pragma unroll
    for (int ks = 0; ks < 2; ks++)
        #pragma unroll
        for (int ntp = 0; ntp < 2; ntp++) {
            MMA(acc[0][2*ntp],   a[ks][0], b[ks][ntp][0], b[ks][ntp][1]);
            MMA(acc[1][2*ntp],   a[ks][1], b[ks][ntp][0], b[ks][ntp][1]);
            MMA(acc[0][2*ntp+1], a[ks][0], b[ks][ntp][2], b[ks][ntp][3]);
            MMA(acc[1][2*ntp+1], a[ks][1], b[ks][ntp][2], b[ks][ntp][3]);
        }
}
__device__ __forceinline__ void compute1(uint32_t buf, uint32_t laneB, int warpN,
                                         int lid, float acc[2][4][4]) {
    const int arow = lid & 15, ka = (lid >> 4) & 1;
    const uint32_t bB = buf + ATILE + warpN * 64 + laneB;
    uint32_t a[2][2][4], b[2][2][4];
    #pragma unroll
    for (int ks = 0; ks < 2; ks++) {
        #pragma unroll
        for (int mt = 0; mt < 2; mt++)
            LDM_X4(a[ks][mt], buf + (mt*16 + arow) * PITCH + ks*32 + ka*16);
        #pragma unroll
        for (int ntp = 0; ntp < 2; ntp++)
            LDM_X4T(b[ks][ntp], bB + ks * 16 * PITCHB + ntp * 32);
    }
    mma_burst(a, b, acc);
}
__device__ __forceinline__ void compute2(uint32_t buf, uint32_t laneB, uint32_t hbase, int c2,
                                         int warpN, int lid, float acc[2][4][4]) {
    const int arow = lid & 15, ka = (lid >> 4) & 1;
    const uint32_t bB = buf + ATILE + warpN * 64 + laneB;
    uint32_t a[2][2][4], b[2][2][4];
    #pragma unroll
    for (int ks = 0; ks < 2; ks++) {
        #pragma unroll
        for (int mt = 0; mt < 2; mt++)
            LDM_X4(a[ks][mt], hbase + (mt*16 + arow) * HPITCH + c2*64 + ks*32 + ka*16);
        #pragma unroll
        for (int ntp = 0; ntp < 2; ntp++)
            LDM_X4T(b[ks][ntp], bB + ks * 16 * PITCHB + ntp * 32);
    }
    mma_burst(a, b, acc);
}

// ---------------------------------------------------------------------------
// Fused kernel: per 32-row block, loop active pairs:
//   H = tanh([Fi|Fj] @ Wp + bp) (smem) ; out_acc += H @ Wft[p]
// 2 CTAs/SM to overlap barrier/drain envelopes.
// ---------------------------------------------------------------------------
__global__ __launch_bounds__(NTHREADS, 2)
void fused_mma(const float* __restrict__ features,
               const float* __restrict__ b_pair,
               const float* __restrict__ b_final,
               const int*   __restrict__ NAS,
               float*       __restrict__ out)
{
    const int rowBase = blockIdx.x * BM;
    extern __shared__ char smem[];
    const uint32_t sb = smem_u32(smem);
    const uint32_t hbase = sb + HOFF;
    const int tid = threadIdx.x, wid = tid >> 5, lid = tid & 31;
    const int warpN = wid;
    const int g = lid >> 2, t = lid & 3;

    // ldmatrix.trans lane address offset within warp's B block
    const uint32_t laneB = (uint32_t)(((lid & 7) + ((lid >> 3) & 1) * 8) * PITCHB
                                      + ((lid >> 4) * 8) * 2);

    // A-loader lane mapping (256 threads; 8/row x 4 fp32)
    const int arow = tid >> 3, aq = tid & 7;
    const uint32_t adofs = arow * PITCH + aq * 8;
    const size_t   arofs = (size_t)arow * EMBED + aq * 4;

    int plist[PAIRS], nact = 0;
    #pragma unroll
    for (int p = 0; p < PAIRS; p++)
        if (pair_on(NAS, p)) plist[nact++] = p;

    float acc2[2][4][4];
    #pragma unroll
    for (int i = 0; i < 2; i++)
        #pragma unroll
        for (int j = 0; j < 4; j++)
            #pragma unroll
            for (int e = 0; e < 4; e++) acc2[i][j][e] = 0.0f;

    for (int pi = 0; pi < nact; pi++) {
        const int p = plist[pi];
        const float* Fi = features + ((size_t)c_pi[p] * MROWS + rowBase) * EMBED;
        const float* Fj = features + ((size_t)c_pj[p] * MROWS + rowBase) * EMBED;
        const __half* WB = g_Wp16 + (size_t)p * KPAIR * EMBED;   // [k][n]

        float acc1[2][4][4];
        #pragma unroll
        for (int i = 0; i < 2; i++)
            #pragma unroll
            for (int j = 0; j < 4; j++)
                #pragma unroll
                for (int e = 0; e < 4; e++) acc1[i][j][e] = 0.0f;

        // ---- GEMM1: 16 chunks over K=512, triple-buffered ----
        float4 rA;
        rA = *reinterpret_cast<const float4*>(Fi + arofs);
        sts_cvt(smem, 0, adofs, rA);
        cp_bk(sb, tid, WB); CP_COMMIT();
        rA = *reinterpret_cast<const float4*>(Fi + arofs + KC);
        cp_bk(sb + BUFB, tid, WB + (size_t)KC * EMBED); CP_COMMIT();

        for (int c = 0; c < NCH1; c++) {
            if (c + 1 < NCH1) sts_cvt(smem, ((c + 1) % 3) * BUFB, adofs, rA);
            if (c + 2 < NCH1) {
                const int k0 = (c + 2) * KC;
                const float* base = (k0 < EMBED) ? Fi : Fj;
                rA = *reinterpret_cast<const float4*>(base + arofs + (k0 & (EMBED - 1)));
            }
            if (c + 1 < NCH1) { CP_WAIT(1); } else { CP_WAIT(0); }
            __syncthreads();
            if (c + 2 < NCH1) {
                cp_bk(sb + ((c + 2) % 3) * BUFB, tid, WB + (size_t)(c + 2) * KC * EMBED);
                CP_COMMIT();
            }
            compute1(sb + (c % 3) * BUFB, laneB, warpN, lid, acc1);
        }

        // ---- H epilogue: bias + tanh -> fp16 into smem H ----
        #pragma unroll
        for (int mt = 0; mt < 2; mt++) {
            const int r0 = mt * 16 + g;
            char* hrow0 = smem + HOFF + (size_t)r0 * HPITCH;
            char* hrow1 = hrow0 + 8 * HPITCH;
            #pragma unroll
            for (int nt = 0; nt < 4; nt++) {
                const int colP = warpN * 32 + nt * 8 + 2 * t;
                const float b0 = __ldg(&b_pair[p * EMBED + colP]);
                const float b1 = __ldg(&b_pair[p * EMBED + colP + 1]);
                *reinterpret_cast<__half2*>(hrow0 + colP * 2) =
                    __floats2half2_rn(tanhf(acc1[mt][nt][0] + b0), tanhf(acc1[mt][nt][1] + b1));
                *reinterpret_cast<__half2*>(hrow1 + colP * 2) =
                    __floats2half2_rn(tanhf(acc1[mt][nt][2] + b0), tanhf(acc1[mt][nt][3] + b1));
            }
        }
        __syncthreads();   // H visible; GEMM1 buffers no longer read

        // ---- GEMM2: 8 chunks over this pair's 256-wide K segment ----
        const __half* WF = g_Wf16 + (size_t)p * EMBED * EMBED;   // rows k=p*256..
        cp_bk(sb, tid, WF); CP_COMMIT();
        cp_bk(sb + BUFB, tid, WF + (size_t)KC * EMBED); CP_COMMIT();
        for (int c = 0; c < NCH2; c++) {
            if (c + 1 < NCH2) { CP_WAIT(1); } else { CP_WAIT(0); }
            __syncthreads();
            if (c + 2 < NCH2) {
                cp_bk(sb + ((c + 2) % 3) * BUFB, tid, WF + (size_t)(c + 2) * KC * EMBED);
                CP_COMMIT();
            }
            compute2(sb + (c % 3) * BUFB, laneB, hbase, c, warpN, lid, acc2);
        }
        __syncthreads();   // buffers/H free before next pair
    }

    // ---- final epilogue: + b_final, fp32 out ----
    #pragma unroll
    for (int mt = 0; mt < 2; mt++) {
        const int r0 = rowBase + mt * 16 + g;
        #pragma unroll
        for (int nt = 0; nt < 4; nt++) {
            const int colG = warpN * 32 + nt * 8 + 2 * t;
            const float b0 = __ldg(&b_final[colG]);
            const float b1 = __ldg(&b_final[colG + 1]);
            float2 v0 = make_float2(acc2[mt][nt][0] + b0, acc2[mt][nt][1] + b1);
            float2 v1 = make_float2(acc2[mt][nt][2] + b0, acc2[mt][nt][3] + b1);
            *reinterpret_cast<float2*>(out + (size_t)r0 * EMBED + colG)       = v0;
            *reinterpret_cast<float2*>(out + (size_t)(r0 + 8) * EMBED + colG) = v1;
        }
    }
}

extern "C" void kernel_launch(void* const* d_in, const int* in_sizes, int n_in,
                              void* d_out, int out_size)
{
    const float* features = (const float*)d_in[0];
    const float* W_pair   = (const float*)d_in[1];
    const float* b_pair   = (const float*)d_in[2];
    const float* W_final  = (const float*)d_in[3];
    const float* b_final  = (const float*)d_in[4];
    const int*   NAS      = (const int*)d_in[5];
    float* out = (float*)d_out;

    cudaFuncSetAttribute(fused_mma, cudaFuncAttributeMaxDynamicSharedMemorySize, SMEM_BYTES);

    const int nvec = (int)((NP1 + NP2) / 4);                 // 737280 float4s
    prep_convert<<<nvec / 256, 256>>>(W_pair, W_final, NAS);

    fused_mma<<<dim3(MROWS/BM), NTHREADS, SMEM_BYTES>>>(features, b_pair, b_final, NAS, out);
}

// round 16
// speedup vs baseline: 1.4859x; 1.4859x over previous
#include <cuda_runtime.h>
#include <cuda_fp16.h>
#include <cstdint>
#include <math.h>

#define EMBED 256
#define PAIRS 15
#define MROWS 16384
#define KPAIR 512
#define KFIN  3840

#define BM 64
#define KC 32
#define NTHREADS 512
#define PITCH 80                          // A smem row: 32 fp16 = 64B + 16B pad
#define ATILE (64 * PITCH)                // 5120 B
#define PITCHB 528                        // B smem row: 256 fp16 = 512B + 16B pad
#define BTILE (KC * PITCHB)               // 16896 B   [k][n] natural layout
#define BUFB  (ATILE + BTILE)             // 22016 B
#define NBUF  6
#define HPITCH 528
#define HOFF  (NBUF * BUFB)               // 132096
#define SMEM_BYTES (HOFF + 64 * HPITCH)   // 165888

#define NCH1 (KPAIR / KC)                 // 16
#define NCH2 (EMBED / KC)                 // 8

// ---- fp16 weights, original [k][n] layouts (allocation-guard-safe) ----
static __device__ __half g_Wp16[(size_t)PAIRS * KPAIR * EMBED];  // [p][k][n]
static __device__ __half g_Wf16[(size_t)KFIN * EMBED];           // [k][n]

__constant__ int c_pi[PAIRS] = {0,0,0,0,0,1,1,1,1,2,2,2,3,3,4};
__constant__ int c_pj[PAIRS] = {1,2,3,4,5,2,3,4,5,3,4,5,4,5,5};

__device__ __forceinline__ bool pair_on(const int* __restrict__ NAS, int p) {
    int i = c_pi[p], j = c_pj[p];
    int ni = (i < 2) ? 1 : __ldg(&NAS[i]);
    int nj = (j < 2) ? 1 : __ldg(&NAS[j]);
    return (ni != 0) && (nj != 0);
}
__device__ __forceinline__ uint32_t smem_u32(const void* p) {
    uint32_t a;
    asm("{ .reg .u64 t; cvta.to.shared.u64 t, %1; cvt.u32.u64 %0, t; }" : "=r"(a) : "l"(p));
    return a;
}

// ---- base-target PTX primitives (sm_80 baseline; valid on plain sm_103) ----
__device__ __forceinline__ void cp16(uint32_t dst, const void* src) {
    asm volatile("cp.async.cg.shared.global [%0], [%1], 16;" :: "r"(dst), "l"(src));
}
#define CP_COMMIT()      asm volatile("cp.async.commit_group;" ::: "memory")
#define CP_WAIT(n)       asm volatile("cp.async.wait_group %0;" :: "n"(n) : "memory")
#define LDM_X4(r, addr) \
    asm volatile("ldmatrix.sync.aligned.m8n8.x4.shared.b16 {%0,%1,%2,%3}, [%4];" \
        : "=r"((r)[0]), "=r"((r)[1]), "=r"((r)[2]), "=r"((r)[3]) : "r"(addr))
#define LDM_X4T(r, addr) \
    asm volatile("ldmatrix.sync.aligned.m8n8.x4.trans.shared.b16 {%0,%1,%2,%3}, [%4];" \
        : "=r"((r)[0]), "=r"((r)[1]), "=r"((r)[2]), "=r"((r)[3]) : "r"(addr))
#define MMA(d, a, b0, b1) \
    asm volatile("mma.sync.aligned.m16n8k16.row.col.f32.f16.f16.f32 " \
        "{%0,%1,%2,%3}, {%4,%5,%6,%7}, {%8,%9}, {%0,%1,%2,%3};" \
        : "+f"((d)[0]), "+f"((d)[1]), "+f"((d)[2]), "+f"((d)[3]) \
        : "r"((a)[0]), "r"((a)[1]), "r"((a)[2]), "r"((a)[3]), "r"(b0), "r"(b1))

// ---------------------------------------------------------------------------
// Prep: elementwise fp32 -> fp16 convert, gated on active pairs/segments.
// ---------------------------------------------------------------------------
#define NP1 ((size_t)PAIRS * KPAIR * EMBED)   // 1966080
#define NP2 ((size_t)KFIN * EMBED)            //  983040
__global__ void prep_convert(const float* __restrict__ W_pair,
                             const float* __restrict__ W_final,
                             const int*   __restrict__ NAS) {
    size_t i = ((size_t)blockIdx.x * blockDim.x + threadIdx.x) * 4;
    const float* src; __half* dst; size_t o;
    if (i < NP1) {
        o = i;
        int p = (int)(o / ((size_t)KPAIR * EMBED));
        if (!pair_on(NAS, p)) return;
        src = W_pair; dst = g_Wp16;
    } else {
        o = i - NP1;
        int p = (int)(o >> 8) >> 8;   // k = o/256 ; segment = k/256
        if (!pair_on(NAS, p)) return;
        src = W_final; dst = g_Wf16;
    }
    float4 v = *reinterpret_cast<const float4*>(src + o);
    __half2 h0 = __floats2half2_rn(v.x, v.y);
    __half2 h1 = __floats2half2_rn(v.z, v.w);
    *reinterpret_cast<__half2*>(dst + o)     = h0;
    *reinterpret_cast<__half2*>(dst + o + 2) = h1;
}

// ---------------------------------------------------------------------------
// Loaders
// ---------------------------------------------------------------------------
// A: 64 rows x 32 k fp32 -> fp16; all 512 threads, 4 fp32 each (8/row).
__device__ __forceinline__ void sts_cvt(char* smem, int bufofs, uint32_t dofs,
                                        const float4 v) {
    unsigned short h[4];
    h[0] = __half_as_ushort(__float2half_rn(v.x));
    h[1] = __half_as_ushort(__float2half_rn(v.y));
    h[2] = __half_as_ushort(__float2half_rn(v.z));
    h[3] = __half_as_ushort(__float2half_rn(v.w));
    *reinterpret_cast<uint2*>(smem + bufofs + dofs) =
        make_uint2((uint32_t)h[0] | ((uint32_t)h[1] << 16),
                   (uint32_t)h[2] | ((uint32_t)h[3] << 16));
}
// B tile: [32 k][256 n] fp16, contiguous 512B rows; 16 threads/row x 32B.
__device__ __forceinline__ void cp_bk(uint32_t buf, int tid, const __half* bsrc) {
    const int row = tid >> 4, c = tid & 15;
    const uint32_t d = buf + ATILE + row * PITCHB + c * 32;
    const __half* s = bsrc + (size_t)row * EMBED + c * 16;
    cp16(d, s); cp16(d + 16, s + 8);
}

// ---------------------------------------------------------------------------
// Compute. 16 warps: warpM = wid&1 (32 rows), warpN = wid>>1 (32 of 256 cols).
// ---------------------------------------------------------------------------
__device__ __forceinline__ void mma_burst(const uint32_t a[2][2][4],
                                          const uint32_t b[2][2][4],
                                          float acc[2][4][4]) {
    #pragma unroll
    for (int ks = 0; ks < 2; ks++)
        #pragma unroll
        for (int ntp = 0; ntp < 2; ntp++) {
            MMA(acc[0][2*ntp],   a[ks][0], b[ks][ntp][0], b[ks][ntp][1]);
            MMA(acc[1][2*ntp],   a[ks][1], b[ks][ntp][0], b[ks][ntp][1]);
            MMA(acc[0][2*ntp+1], a[ks][0], b[ks][ntp][2], b[ks][ntp][3]);
            MMA(acc[1][2*ntp+1], a[ks][1], b[ks][ntp][2], b[ks][ntp][3]);
        }
}
__device__ __forceinline__ void compute1(uint32_t buf, uint32_t laneB, int warpM, int warpN,
                                         int lid, float acc[2][4][4]) {
    const int arow = lid & 15, ka = (lid >> 4) & 1;
    const uint32_t bB = buf + ATILE + warpN * 64 + laneB;
    uint32_t a[2][2][4], b[2][2][4];
    #pragma unroll
    for (int ks = 0; ks < 2; ks++) {
        #pragma unroll
        for (int mt = 0; mt < 2; mt++)
            LDM_X4(a[ks][mt], buf + (warpM*32 + mt*16 + arow) * PITCH + ks*32 + ka*16);
        #pragma unroll
        for (int ntp = 0; ntp < 2; ntp++)
            LDM_X4T(b[ks][ntp], bB + ks * 16 * PITCHB + ntp * 32);
    }
    mma_burst(a, b, acc);
}
__device__ __forceinline__ void compute2(uint32_t buf, uint32_t laneB, uint32_t hbase, int c2,
                                         int warpM, int warpN, int lid, float acc[2][4][4]) {
    const int arow = lid & 15, ka = (lid >> 4) & 1;
    const uint32_t bB = buf + ATILE + warpN * 64 + laneB;
    uint32_t a[2][2][4], b[2][2][4];
    #pragma unroll
    for (int ks = 0; ks < 2; ks++) {
        #pragma unroll
        for (int mt = 0; mt < 2; mt++)
            LDM_X4(a[ks][mt], hbase + (warpM*32 + mt*16 + arow) * HPITCH + c2*64 + ks*32 + ka*16);
        #pragma unroll
        for (int ntp = 0; ntp < 2; ntp++)
            LDM_X4T(b[ks][ntp], bB + ks * 16 * PITCHB + ntp * 32);
    }
    mma_burst(a, b, acc);
}

// ---------------------------------------------------------------------------
// Fused kernel: per 64-row block, loop active pairs:
//   H = tanh([Fi|Fj] @ Wp + bp) (smem) ; out_acc += H @ Wft[p]
// 2 chunks per barrier, 6-buffer ring (reuse distance = 2 syncs).
// ---------------------------------------------------------------------------
__global__ __launch_bounds__(NTHREADS, 1)
void fused_mma(const float* __restrict__ features,
               const float* __restrict__ b_pair,
               const float* __restrict__ b_final,
               const int*   __restrict__ NAS,
               float*       __restrict__ out)
{
    const int rowBase = blockIdx.x * BM;
    extern __shared__ char smem[];
    const uint32_t sb = smem_u32(smem);
    const uint32_t hbase = sb + HOFF;
    const int tid = threadIdx.x, wid = tid >> 5, lid = tid & 31;
    const int warpM = wid & 1, warpN = wid >> 1;
    const int g = lid >> 2, t = lid & 3;

    // ldmatrix.trans lane address offset within warp's B block
    const uint32_t laneB = (uint32_t)(((lid & 7) + ((lid >> 3) & 1) * 8) * PITCHB
                                      + ((lid >> 4) * 8) * 2);

    // A-loader lane mapping (512 threads; 8/row x 4 fp32)
    const int arow = tid >> 3, aq = tid & 7;
    const uint32_t adofs = arow * PITCH + aq * 8;
    const size_t   arofs = (size_t)arow * EMBED + aq * 4;

    int plist[PAIRS], nact = 0;
    #pragma unroll
    for (int p = 0; p < PAIRS; p++)
        if (pair_on(NAS, p)) plist[nact++] = p;

    float acc2[2][4][4];
    #pragma unroll
    for (int i = 0; i < 2; i++)
        #pragma unroll
        for (int j = 0; j < 4; j++)
            #pragma unroll
            for (int e = 0; e < 4; e++) acc2[i][j][e] = 0.0f;

    for (int pi = 0; pi < nact; pi++) {
        const int p = plist[pi];
        const float* Fi = features + ((size_t)c_pi[p] * MROWS + rowBase) * EMBED;
        const float* Fj = features + ((size_t)c_pj[p] * MROWS + rowBase) * EMBED;
        const __half* WB = g_Wp16 + (size_t)p * KPAIR * EMBED;   // [k][n]

        float acc1[2][4][4];
        #pragma unroll
        for (int i = 0; i < 2; i++)
            #pragma unroll
            for (int j = 0; j < 4; j++)
                #pragma unroll
                for (int e = 0; e < 4; e++) acc1[i][j][e] = 0.0f;

        // ---- GEMM1: 16 chunks, 2 per barrier, 6-buffer ring ----
        float4 rA0, rA1;
        rA0 = *reinterpret_cast<const float4*>(Fi + arofs);
        rA1 = *reinterpret_cast<const float4*>(Fi + arofs + KC);
        sts_cvt(smem, 0, adofs, rA0);
        sts_cvt(smem, BUFB, adofs, rA1);
        cp_bk(sb,        tid, WB);                         CP_COMMIT();
        cp_bk(sb + BUFB, tid, WB + (size_t)KC * EMBED);    CP_COMMIT();
        rA0 = *reinterpret_cast<const float4*>(Fi + arofs + 2 * KC);
        rA1 = *reinterpret_cast<const float4*>(Fi + arofs + 3 * KC);

        for (int cc = 0; cc < NCH1; cc += 2) {
            if (cc + 2 < NCH1) {
                const int b2 = (cc + 2) % NBUF, b3 = (cc + 3) % NBUF;
                sts_cvt(smem, b2 * BUFB, adofs, rA0);
                cp_bk(sb + b2 * BUFB, tid, WB + (size_t)(cc + 2) * KC * EMBED); CP_COMMIT();
                sts_cvt(smem, b3 * BUFB, adofs, rA1);
                cp_bk(sb + b3 * BUFB, tid, WB + (size_t)(cc + 3) * KC * EMBED); CP_COMMIT();
                if (cc + 4 < NCH1) {
                    const int k0 = (cc + 4) * KC, k1 = (cc + 5) * KC;
                    rA0 = *reinterpret_cast<const float4*>(
                        ((k0 < EMBED) ? Fi : Fj) + arofs + (k0 & (EMBED - 1)));
                    rA1 = *reinterpret_cast<const float4*>(
                        ((k1 < EMBED) ? Fi : Fj) + arofs + (k1 & (EMBED - 1)));
                }
                CP_WAIT(2);
            } else {
                CP_WAIT(0);
            }
            __syncthreads();
            compute1(sb + (cc % NBUF) * BUFB,       laneB, warpM, warpN, lid, acc1);
            compute1(sb + ((cc + 1) % NBUF) * BUFB, laneB, warpM, warpN, lid, acc1);
        }

        // GEMM2 chunks 0,1 prefetch (bufs 16%6=4, 17%6=5) — fly during epilogue
        const __half* WF = g_Wf16 + (size_t)p * EMBED * EMBED;
        cp_bk(sb + 4 * BUFB, tid, WF);                      CP_COMMIT();
        cp_bk(sb + 5 * BUFB, tid, WF + (size_t)KC * EMBED); CP_COMMIT();

        // ---- H epilogue: bias + tanh -> fp16 into smem H ----
        #pragma unroll
        for (int mt = 0; mt < 2; mt++) {
            const int r0 = warpM * 32 + mt * 16 + g;
            char* hrow0 = smem + HOFF + (size_t)r0 * HPITCH;
            char* hrow1 = hrow0 + 8 * HPITCH;
            #pragma unroll
            for (int nt = 0; nt < 4; nt++) {
                const int colP = warpN * 32 + nt * 8 + 2 * t;
                const float b0 = __ldg(&b_pair[p * EMBED + colP]);
                const float b1 = __ldg(&b_pair[p * EMBED + colP + 1]);
                *reinterpret_cast<__half2*>(hrow0 + colP * 2) =
                    __floats2half2_rn(tanhf(acc1[mt][nt][0] + b0), tanhf(acc1[mt][nt][1] + b1));
                *reinterpret_cast<__half2*>(hrow1 + colP * 2) =
                    __floats2half2_rn(tanhf(acc1[mt][nt][2] + b0), tanhf(acc1[mt][nt][3] + b1));
            }
        }
        __syncthreads();   // H visible; GEMM1 buffers no longer read

        // ---- GEMM2: 8 chunks, 2 per barrier, ring continues at index 16 ----
        for (int cc = 0; cc < NCH2; cc += 2) {
            if (cc + 2 < NCH2) {
                const int b2 = (16 + cc + 2) % NBUF, b3 = (16 + cc + 3) % NBUF;
                cp_bk(sb + b2 * BUFB, tid, WF + (size_t)(cc + 2) * KC * EMBED); CP_COMMIT();
                cp_bk(sb + b3 * BUFB, tid, WF + (size_t)(cc + 3) * KC * EMBED); CP_COMMIT();
                CP_WAIT(2);
            } else {
                CP_WAIT(0);
            }
            __syncthreads();
            compute2(sb + ((16 + cc) % NBUF) * BUFB,     laneB, hbase, cc,     warpM, warpN, lid, acc2);
            compute2(sb + ((16 + cc + 1) % NBUF) * BUFB, laneB, hbase, cc + 1, warpM, warpN, lid, acc2);
        }
        __syncthreads();   // buffers/H free before next pair
    }

    // ---- final epilogue: + b_final, fp32 out ----
    #pragma unroll
    for (int mt = 0; mt < 2; mt++) {
        const int r0 = rowBase + warpM * 32 + mt * 16 + g;
        #pragma unroll
        for (int nt = 0; nt < 4; nt++) {
            const int colG = warpN * 32 + nt * 8 + 2 * t;
            const float b0 = __ldg(&b_final[colG]);
            const float b1 = __ldg(&b_final[colG + 1]);
            float2 v0 = make_float2(acc2[mt][nt][0] + b0, acc2[mt][nt][1] + b1);
            float2 v1 = make_float2(acc2[mt][nt][2] + b0, acc2[mt][nt][3] + b1);
            *reinterpret_cast<float2*>(out + (size_t)r0 * EMBED + colG)       = v0;
            *reinterpret_cast<float2*>(out + (size_t)(r0 + 8) * EMBED + colG) = v1;
        }
    }
}

extern "C" void kernel_launch(void* const* d_in, const int* in_sizes, int n_in,
                              void* d_out, int out_size)
{
    const float* features = (const float*)d_in[0];
    const float* W_pair   = (const float*)d_in[1];
    const float* b_pair   = (const float*)d_in[2];
    const float* W_final  = (const float*)d_in[3];
    const float* b_final  = (const float*)d_in[4];
    const int*   NAS      = (const int*)d_in[5];
    float* out = (float*)d_out;

    cudaFuncSetAttribute(fused_mma, cudaFuncAttributeMaxDynamicSharedMemorySize, SMEM_BYTES);

    const int nvec = (int)((NP1 + NP2) / 4);                 // 737280 float4s
    prep_convert<<<nvec / 256, 256>>>(W_pair, W_final, NAS);

    fused_mma<<<dim3(MROWS/BM), NTHREADS, SMEM_BYTES>>>(features, b_pair, b_final, NAS, out);
}